// round 10
// baseline (speedup 1.0000x reference)
#include <cuda_runtime.h>
#include <cuda_bf16.h>
#include <mma.h>
#include <cstdint>

using namespace nvcuda;

#define N_NODES 50000
#define E_EDGES 800000
#define INF_    256
#define OUTF_   32
#define HEADS_  8
#define HF_     256   // HEADS_ * OUTF_
#define MPAD    50048 // 391 * 128, padded row count for boundless fragment ops

// ---------------- scratch (static __device__, no allocation) ----------------
__device__ __nv_bfloat16 g_wh[HF_ * INF_];               // W hi, [j=head*32+f][k]
__device__ __nv_bfloat16 g_wl[HF_ * INF_];               // W lo
__device__ __nv_bfloat16 g_xh[(size_t)MPAD * INF_];      // x hi (padded, zeros)
__device__ __nv_bfloat16 g_xl[(size_t)MPAD * INF_];      // x lo
__device__ float g_h[(size_t)MPAD * HF_];                // transformed features
__device__ float g_ssrc[N_NODES * HEADS_];
__device__ float g_sdst[N_NODES * HEADS_];
__device__ int   g_deg[N_NODES];
__device__ int   g_cursor[N_NODES];
__device__ int   g_rowstart[N_NODES + 1];
__device__ int   g_csr_src[E_EDGES];

// ---------------- W pack + bf16 split: [H,256,32] -> [j=256][k=256] ----------
__global__ void k_wsplit(const float* __restrict__ W) {
    int idx = blockIdx.x * blockDim.x + threadIdx.x;     // idx = j*256 + k
    if (idx >= HF_ * INF_) return;
    int j = idx >> 8;
    int k = idx & 255;
    int head = j >> 5;
    int f = j & 31;
    float w = W[head * (INF_ * OUTF_) + k * OUTF_ + f];
    __nv_bfloat16 hi = __float2bfloat16(w);
    float r = w - __bfloat162float(hi);
    g_wh[idx] = hi;
    g_wl[idx] = __float2bfloat16(r);
}

// ---------------- x bf16 split (with zero padding rows) ----------------------
__global__ void k_xsplit(const float* __restrict__ x, int M) {
    size_t idx = (size_t)blockIdx.x * blockDim.x + threadIdx.x;  // row*256 + k
    if (idx >= (size_t)MPAD * INF_) return;
    int row = (int)(idx >> 8);
    float v = (row < M) ? x[idx] : 0.f;
    __nv_bfloat16 hi = __float2bfloat16(v);
    float r = v - __bfloat162float(hi);
    g_xh[idx] = hi;
    g_xl[idx] = __float2bfloat16(r);
}

// ---------------- WMMA bf16-split GEMM: g_h = x @ Wt -------------------------
// CTA 128x128, 8 warps (4 row x 2 col), warp tile 32x64 = 2x4 m16n16k16 frags.
// acc += ah*bh + ah*bl + al*bh   (al*bl term ~2^-18, dropped)
__global__ void __launch_bounds__(256) k_gemm_wmma() {
    const int warp = threadIdx.x >> 5;
    const int wm = warp & 3;                  // 0..3
    const int wn = warp >> 2;                 // 0..1
    const int m0 = blockIdx.y * 128 + wm * 32;
    const int n0 = blockIdx.x * 128 + wn * 64;

    wmma::fragment<wmma::accumulator, 16, 16, 16, float> acc[2][4];
#pragma unroll
    for (int i = 0; i < 2; i++)
#pragma unroll
        for (int j = 0; j < 4; j++) wmma::fill_fragment(acc[i][j], 0.f);

    wmma::fragment<wmma::matrix_a, 16, 16, 16, __nv_bfloat16, wmma::row_major> ah[2], al[2];
    wmma::fragment<wmma::matrix_b, 16, 16, 16, __nv_bfloat16, wmma::col_major> bh[4], bl[4];

    for (int k0 = 0; k0 < INF_; k0 += 16) {
#pragma unroll
        for (int i = 0; i < 2; i++) {
            const size_t ao = (size_t)(m0 + 16 * i) * INF_ + k0;
            wmma::load_matrix_sync(ah[i], &g_xh[ao], INF_);
            wmma::load_matrix_sync(al[i], &g_xl[ao], INF_);
        }
#pragma unroll
        for (int j = 0; j < 4; j++) {
            const size_t bo = (size_t)(n0 + 16 * j) * INF_ + k0;
            wmma::load_matrix_sync(bh[j], &g_wh[bo], INF_);
            wmma::load_matrix_sync(bl[j], &g_wl[bo], INF_);
        }
#pragma unroll
        for (int i = 0; i < 2; i++)
#pragma unroll
            for (int j = 0; j < 4; j++) {
                wmma::mma_sync(acc[i][j], ah[i], bh[j], acc[i][j]);
                wmma::mma_sync(acc[i][j], ah[i], bl[j], acc[i][j]);
                wmma::mma_sync(acc[i][j], al[i], bh[j], acc[i][j]);
            }
    }

#pragma unroll
    for (int i = 0; i < 2; i++)
#pragma unroll
        for (int j = 0; j < 4; j++)
            wmma::store_matrix_sync(&g_h[(size_t)(m0 + 16 * i) * HF_ + n0 + 16 * j],
                                    acc[i][j], HF_, wmma::mem_row_major);
}

// ---------------- per-(node,head) attention logits ---------------------------
__global__ void k_scores(const float* __restrict__ a_src,
                         const float* __restrict__ a_dst, int NN) {
    int t = blockIdx.x * blockDim.x + threadIdx.x;       // t = n*8 + head
    if (t >= NN * HEADS_) return;
    int n = t >> 3;
    int head = t & 7;
    const float4* hv = (const float4*)&g_h[(size_t)n * HF_ + head * OUTF_];
    const float4* sv = (const float4*)&a_src[head * OUTF_];
    const float4* dv = (const float4*)&a_dst[head * OUTF_];
    float ss = 0.f, sd = 0.f;
#pragma unroll
    for (int i = 0; i < 8; i++) {
        float4 h4 = hv[i], s4 = sv[i], d4 = dv[i];
        ss += h4.x * s4.x + h4.y * s4.y + h4.z * s4.z + h4.w * s4.w;
        sd += h4.x * d4.x + h4.y * d4.y + h4.z * d4.z + h4.w * d4.w;
    }
    g_ssrc[t] = ss;
    g_sdst[t] = sd;
}

// ---------------- CSR build --------------------------------------------------
__global__ void k_zero(int NN) {
    int t = blockIdx.x * blockDim.x + threadIdx.x;
    if (t < NN) { g_deg[t] = 0; g_cursor[t] = 0; }
}

__global__ void k_count(const int* __restrict__ dst, int E) {
    int e = blockIdx.x * blockDim.x + threadIdx.x;
    if (e < E) atomicAdd(&g_deg[dst[e]], 1);
}

// single-block shfl-based exclusive scan over g_deg -> g_rowstart
__global__ void k_scan(int NN) {
    __shared__ int warpsum[32];
    __shared__ int carry;
    const int tid = threadIdx.x;
    const int lane = tid & 31;
    const int wid = tid >> 5;
    if (tid == 0) carry = 0;
    __syncthreads();
    for (int base = 0; base < NN; base += 1024) {
        int v = (base + tid < NN) ? g_deg[base + tid] : 0;
        int s = v;
#pragma unroll
        for (int o = 1; o < 32; o <<= 1) {
            int t = __shfl_up_sync(0xffffffffu, s, o);
            if (lane >= o) s += t;
        }
        if (lane == 31) warpsum[wid] = s;
        __syncthreads();
        if (wid == 0) {
            int ws = warpsum[lane];
#pragma unroll
            for (int o = 1; o < 32; o <<= 1) {
                int t = __shfl_up_sync(0xffffffffu, ws, o);
                if (lane >= o) ws += t;
            }
            warpsum[lane] = ws;
        }
        __syncthreads();
        int excl = s - v + (wid > 0 ? warpsum[wid - 1] : 0) + carry;
        if (base + tid < NN) g_rowstart[base + tid] = excl;
        int total = warpsum[31];
        __syncthreads();
        if (tid == 0) carry += total;
        __syncthreads();
    }
    if (tid == 0) g_rowstart[NN] = carry;
}

__global__ void k_fill(const int* __restrict__ src, const int* __restrict__ dst, int E) {
    int e = blockIdx.x * blockDim.x + threadIdx.x;
    if (e >= E) return;
    int d = dst[e];
    int pos = atomicAdd(&g_cursor[d], 1);
    g_csr_src[g_rowstart[d] + pos] = src[e];
}

// ---------------- fused softmax + aggregation --------------------------------
// block per node (256 threads), warp per head, lane per output feature.
__global__ void k_aggr(float* __restrict__ out) {
    const int n = blockIdx.x;
    const int head = threadIdx.x >> 5;
    const int lane = threadIdx.x & 31;
    __shared__ int s_rs, s_re;
    if (threadIdx.x == 0) {
        s_rs = g_rowstart[n];
        s_re = g_rowstart[n + 1];
    }
    __syncthreads();
    const int rs = s_rs, re = s_re;
    const float sd = g_sdst[n * HEADS_ + head];

    // phase 1: online softmax (max + sum) over incoming edges, lanes strided
    float m = -1e30f, ssum = 0.f;
    for (int i = rs + lane; i < re; i += 32) {
        int s = g_csr_src[i];
        float ea = g_ssrc[s * HEADS_ + head] + sd;
        ea = ea > 0.f ? ea : 0.2f * ea;
        if (ea > m) { ssum *= __expf(m - ea); m = ea; }
        ssum += __expf(ea - m);
    }
#pragma unroll
    for (int off = 16; off; off >>= 1) {
        float m2 = __shfl_xor_sync(0xffffffffu, m, off);
        float s2 = __shfl_xor_sync(0xffffffffu, ssum, off);
        float mn = fmaxf(m, m2);
        ssum = ssum * __expf(m - mn) + s2 * __expf(m2 - mn);
        m = mn;
    }
    const float inv = 1.0f / (ssum + 1e-8f);

    // phase 2: weighted gather, unrolled x4 for MLP against L2-hit latency
    float acc = 0.f;
    int i = rs;
    for (; i + 4 <= re; i += 4) {
        int s0 = g_csr_src[i + 0];
        int s1 = g_csr_src[i + 1];
        int s2 = g_csr_src[i + 2];
        int s3 = g_csr_src[i + 3];
        float a0 = g_ssrc[s0 * HEADS_ + head] + sd;
        float a1 = g_ssrc[s1 * HEADS_ + head] + sd;
        float a2 = g_ssrc[s2 * HEADS_ + head] + sd;
        float a3 = g_ssrc[s3 * HEADS_ + head] + sd;
        float h0 = g_h[(size_t)s0 * HF_ + head * OUTF_ + lane];
        float h1 = g_h[(size_t)s1 * HF_ + head * OUTF_ + lane];
        float h2 = g_h[(size_t)s2 * HF_ + head * OUTF_ + lane];
        float h3 = g_h[(size_t)s3 * HF_ + head * OUTF_ + lane];
        a0 = a0 > 0.f ? a0 : 0.2f * a0;
        a1 = a1 > 0.f ? a1 : 0.2f * a1;
        a2 = a2 > 0.f ? a2 : 0.2f * a2;
        a3 = a3 > 0.f ? a3 : 0.2f * a3;
        float c0 = __expf(a0 - m) * inv;
        float c1 = __expf(a1 - m) * inv;
        float c2 = __expf(a2 - m) * inv;
        float c3 = __expf(a3 - m) * inv;
        acc = fmaf(c0, h0, acc);
        acc = fmaf(c1, h1, acc);
        acc = fmaf(c2, h2, acc);
        acc = fmaf(c3, h3, acc);
    }
    for (; i < re; i++) {
        int s = g_csr_src[i];
        float ea = g_ssrc[s * HEADS_ + head] + sd;
        ea = ea > 0.f ? ea : 0.2f * ea;
        float c = __expf(ea - m) * inv;
        acc = fmaf(c, g_h[(size_t)s * HF_ + head * OUTF_ + lane], acc);
    }
    out[(size_t)n * HF_ + head * OUTF_ + lane] = acc;
}

// ---------------- launch -----------------------------------------------------
extern "C" void kernel_launch(void* const* d_in, const int* in_sizes, int n_in,
                              void* d_out, int out_size) {
    const float* x     = (const float*)d_in[0];
    const int*   ei    = (const int*)d_in[1];
    const float* W     = (const float*)d_in[2];
    const float* a_src = (const float*)d_in[3];
    const float* a_dst = (const float*)d_in[4];
    float* out = (float*)d_out;

    const int M = in_sizes[0] / INF_;     // 50000
    const int E = in_sizes[1] / 2;        // 800000
    const int* src = ei;
    const int* dst = ei + E;

    const int mblocks = (M + 127) / 128;  // 391; mblocks*128 <= MPAD

    k_wsplit<<<(HF_ * INF_ + 255) / 256, 256>>>(W);
    k_xsplit<<<(int)(((size_t)MPAD * INF_ + 255) / 256), 256>>>(x, M);
    k_gemm_wmma<<<dim3(2, mblocks), 256>>>();
    k_scores<<<(M * HEADS_ + 255) / 256, 256>>>(a_src, a_dst, M);
    k_zero<<<(M + 255) / 256, 256>>>(M);
    k_count<<<(E + 255) / 256, 256>>>(dst, E);
    k_scan<<<1, 1024>>>(M);
    k_fill<<<(E + 255) / 256, 256>>>(src, dst, E);
    k_aggr<<<M, 256>>>(out);
}

// round 11
// speedup vs baseline: 1.3507x; 1.3507x over previous
#include <cuda_runtime.h>
#include <cuda_bf16.h>
#include <mma.h>
#include <cstdint>

using namespace nvcuda;

#define N_NODES 50000
#define E_EDGES 800000
#define INF_    256
#define OUTF_   32
#define HEADS_  8
#define HF_     256   // HEADS_ * OUTF_
#define MPAD    50048 // 391 * 128, padded row count for boundless fragment ops

// ---------------- scratch (static __device__, no allocation) ----------------
__device__ __nv_bfloat16 g_wh[HF_ * INF_];               // W hi, [j=head*32+f][k]
__device__ __nv_bfloat16 g_wl[HF_ * INF_];               // W lo
__device__ __nv_bfloat16 g_xh[(size_t)MPAD * INF_];      // x hi (padded, zeros)
__device__ __nv_bfloat16 g_xl[(size_t)MPAD * INF_];      // x lo
__device__ float g_h[(size_t)MPAD * HF_];                // transformed features
__device__ float g_wasrc[HEADS_ * INF_];                 // W @ a_src  [h][k]
__device__ float g_wadst[HEADS_ * INF_];                 // W @ a_dst  [h][k]
__device__ float g_ssrc[N_NODES * HEADS_];
__device__ float g_sdst[N_NODES * HEADS_];
__device__ int   g_deg[N_NODES];
__device__ int   g_cursor[N_NODES];
__device__ int   g_rowstart[N_NODES + 1];
__device__ int   g_csr_src[E_EDGES];

// ---------------- W pack + bf16 split: [H,256,32] -> [j=256][k=256] ----------
__global__ void k_wsplit(const float* __restrict__ W) {
    int idx = blockIdx.x * blockDim.x + threadIdx.x;     // idx = j*256 + k
    if (idx >= HF_ * INF_) return;
    int j = idx >> 8;
    int k = idx & 255;
    int head = j >> 5;
    int f = j & 31;
    float w = W[head * (INF_ * OUTF_) + k * OUTF_ + f];
    __nv_bfloat16 hi = __float2bfloat16(w);
    float r = w - __bfloat162float(hi);
    g_wh[idx] = hi;
    g_wl[idx] = __float2bfloat16(r);
}

// ---------------- wa[h][k] = sum_f W[h][k][f] * a[h][f] ----------------------
__global__ void k_wa(const float* __restrict__ W,
                     const float* __restrict__ a_src,
                     const float* __restrict__ a_dst) {
    int t = blockIdx.x * blockDim.x + threadIdx.x;       // t = h*256 + k
    if (t >= HEADS_ * INF_) return;
    int h = t >> 8;
    int k = t & 255;
    const float* wp = W + h * (INF_ * OUTF_) + k * OUTF_;
    const float* as = a_src + h * OUTF_;
    const float* ad = a_dst + h * OUTF_;
    float ss = 0.f, sd = 0.f;
#pragma unroll
    for (int f = 0; f < OUTF_; f++) {
        float w = wp[f];
        ss = fmaf(w, as[f], ss);
        sd = fmaf(w, ad[f], sd);
    }
    g_wasrc[t] = ss;
    g_wadst[t] = sd;
}

// ---------------- x split + fused attention logits (warp per row) ------------
__global__ void k_xs(const float* __restrict__ x, int M) {
    const int w = (blockIdx.x * blockDim.x + threadIdx.x) >> 5;  // row
    const int lane = threadIdx.x & 31;
    if (w >= MPAD) return;
    const size_t base = (size_t)w * INF_ + lane * 8;
    if (w >= M) {
        uint4 z = make_uint4(0, 0, 0, 0);
        *(uint4*)&g_xh[base] = z;
        *(uint4*)&g_xl[base] = z;
        return;
    }
    float4 v0 = *(const float4*)&x[base];
    float4 v1 = *(const float4*)&x[base + 4];
    float v[8] = {v0.x, v0.y, v0.z, v0.w, v1.x, v1.y, v1.z, v1.w};
    uint32_t hp[4], lp[4];
#pragma unroll
    for (int q = 0; q < 4; q++) {
        __nv_bfloat16 h0 = __float2bfloat16(v[2 * q]);
        __nv_bfloat16 h1 = __float2bfloat16(v[2 * q + 1]);
        float r0 = v[2 * q] - __bfloat162float(h0);
        float r1 = v[2 * q + 1] - __bfloat162float(h1);
        hp[q] = (uint32_t)__bfloat16_as_ushort(h0) |
                ((uint32_t)__bfloat16_as_ushort(__float2bfloat16(r0)) << 0x10 >> 0x10 << 16);
        lp[q] = 0;  // placeholder, rewritten below
        // (rewrite cleanly)
        hp[q] = (uint32_t)__bfloat16_as_ushort(h0) |
                ((uint32_t)__bfloat16_as_ushort(h1) << 16);
        lp[q] = (uint32_t)__bfloat16_as_ushort(__float2bfloat16(r0)) |
                ((uint32_t)__bfloat16_as_ushort(__float2bfloat16(r1)) << 16);
    }
    *(uint4*)&g_xh[base] = make_uint4(hp[0], hp[1], hp[2], hp[3]);
    *(uint4*)&g_xl[base] = make_uint4(lp[0], lp[1], lp[2], lp[3]);

    // attention logits: ts[h] = sum_k x[k]*wa_src[h][k] (partial over 8 k's)
    float ts[HEADS_], td[HEADS_];
#pragma unroll
    for (int h = 0; h < HEADS_; h++) {
        const float4* ws = (const float4*)&g_wasrc[h * INF_ + lane * 8];
        const float4* wd = (const float4*)&g_wadst[h * INF_ + lane * 8];
        float4 s0 = ws[0], s1 = ws[1], d0 = wd[0], d1 = wd[1];
        ts[h] = v[0] * s0.x + v[1] * s0.y + v[2] * s0.z + v[3] * s0.w +
                v[4] * s1.x + v[5] * s1.y + v[6] * s1.z + v[7] * s1.w;
        td[h] = v[0] * d0.x + v[1] * d0.y + v[2] * d0.z + v[3] * d0.w +
                v[4] * d1.x + v[5] * d1.y + v[6] * d1.z + v[7] * d1.w;
    }
#pragma unroll
    for (int off = 16; off; off >>= 1) {
#pragma unroll
        for (int h = 0; h < HEADS_; h++) {
            ts[h] += __shfl_xor_sync(0xffffffffu, ts[h], off);
            td[h] += __shfl_xor_sync(0xffffffffu, td[h], off);
        }
    }
    if (lane == 0) {
#pragma unroll
        for (int h = 0; h < HEADS_; h++) {
            g_ssrc[w * HEADS_ + h] = ts[h];
            g_sdst[w * HEADS_ + h] = td[h];
        }
    }
}

// ---------------- WMMA bf16-split GEMM (smem-staged): g_h = x @ Wt -----------
// CTA 128x128, 8 warps (4 row x 2 col), warp tile 32x64 = 2x4 m16n16k16 frags.
// acc += ah*bh + ah*bl + al*bh   (al*bl ~ 2^-18, dropped). BK=32 staged in smem.
#define LDA 40   // padded smem leading dim (elements); conflict-free for LDSM
__global__ void __launch_bounds__(256) k_gemm_wmma() {
    __shared__ __nv_bfloat16 Ah[128 * LDA], Al[128 * LDA];
    __shared__ __nv_bfloat16 Bh[128 * LDA], Bl[128 * LDA];
    const int tid = threadIdx.x;
    const int warp = tid >> 5;
    const int wm = warp & 3;
    const int wn = warp >> 2;
    const int m0 = blockIdx.y * 128;
    const int n0 = blockIdx.x * 128;

    wmma::fragment<wmma::accumulator, 16, 16, 16, float> acc[2][4];
#pragma unroll
    for (int i = 0; i < 2; i++)
#pragma unroll
        for (int j = 0; j < 4; j++) wmma::fill_fragment(acc[i][j], 0.f);

    for (int k0 = 0; k0 < INF_; k0 += 32) {
        __syncthreads();
#pragma unroll
        for (int u = 0; u < 2; u++) {
            int id = tid + u * 256;          // 0..511
            int row = id >> 2;               // 0..127
            int c8 = (id & 3) * 8;           // col in elements
            size_t ga = (size_t)(m0 + row) * INF_ + k0 + c8;
            size_t gb = (size_t)(n0 + row) * INF_ + k0 + c8;
            *(uint4*)&Ah[row * LDA + c8] = *(const uint4*)&g_xh[ga];
            *(uint4*)&Al[row * LDA + c8] = *(const uint4*)&g_xl[ga];
            *(uint4*)&Bh[row * LDA + c8] = *(const uint4*)&g_wh[gb];
            *(uint4*)&Bl[row * LDA + c8] = *(const uint4*)&g_wl[gb];
        }
        __syncthreads();

#pragma unroll
        for (int ks = 0; ks < 2; ks++) {
            wmma::fragment<wmma::matrix_a, 16, 16, 16, __nv_bfloat16, wmma::row_major> ah[2], al[2];
            wmma::fragment<wmma::matrix_b, 16, 16, 16, __nv_bfloat16, wmma::col_major> bh[4], bl[4];
#pragma unroll
            for (int i = 0; i < 2; i++) {
                int ro = (wm * 32 + i * 16) * LDA + ks * 16;
                wmma::load_matrix_sync(ah[i], &Ah[ro], LDA);
                wmma::load_matrix_sync(al[i], &Al[ro], LDA);
            }
#pragma unroll
            for (int j = 0; j < 4; j++) {
                int ro = (wn * 64 + j * 16) * LDA + ks * 16;
                wmma::load_matrix_sync(bh[j], &Bh[ro], LDA);
                wmma::load_matrix_sync(bl[j], &Bl[ro], LDA);
            }
#pragma unroll
            for (int i = 0; i < 2; i++)
#pragma unroll
                for (int j = 0; j < 4; j++) {
                    wmma::mma_sync(acc[i][j], ah[i], bh[j], acc[i][j]);
                    wmma::mma_sync(acc[i][j], ah[i], bl[j], acc[i][j]);
                    wmma::mma_sync(acc[i][j], al[i], bh[j], acc[i][j]);
                }
        }
    }

#pragma unroll
    for (int i = 0; i < 2; i++)
#pragma unroll
        for (int j = 0; j < 4; j++)
            wmma::store_matrix_sync(
                &g_h[(size_t)(m0 + wm * 32 + 16 * i) * HF_ + n0 + wn * 64 + 16 * j],
                acc[i][j], HF_, wmma::mem_row_major);
}

// ---------------- CSR build --------------------------------------------------
__global__ void k_zero(int NN) {
    int t = blockIdx.x * blockDim.x + threadIdx.x;
    if (t < NN) { g_deg[t] = 0; g_cursor[t] = 0; }
}

__global__ void k_count(const int* __restrict__ dst, int E) {
    int e = blockIdx.x * blockDim.x + threadIdx.x;
    if (e < E) atomicAdd(&g_deg[dst[e]], 1);
}

// single-block shfl scan, 4 elements per thread -> g_rowstart
__global__ void k_scan(int NN) {
    __shared__ int warpsum[32];
    __shared__ int carry;
    const int tid = threadIdx.x;
    const int lane = tid & 31;
    const int wid = tid >> 5;
    if (tid == 0) carry = 0;
    __syncthreads();
    for (int base = 0; base < NN; base += 4096) {
        int i0 = base + tid * 4;
        int v0 = (i0 + 0 < NN) ? g_deg[i0 + 0] : 0;
        int v1 = (i0 + 1 < NN) ? g_deg[i0 + 1] : 0;
        int v2 = (i0 + 2 < NN) ? g_deg[i0 + 2] : 0;
        int v3 = (i0 + 3 < NN) ? g_deg[i0 + 3] : 0;
        int tsum = v0 + v1 + v2 + v3;
        int s = tsum;
#pragma unroll
        for (int o = 1; o < 32; o <<= 1) {
            int t = __shfl_up_sync(0xffffffffu, s, o);
            if (lane >= o) s += t;
        }
        if (lane == 31) warpsum[wid] = s;
        __syncthreads();
        if (wid == 0) {
            int ws = warpsum[lane];
#pragma unroll
            for (int o = 1; o < 32; o <<= 1) {
                int t = __shfl_up_sync(0xffffffffu, ws, o);
                if (lane >= o) ws += t;
            }
            warpsum[lane] = ws;
        }
        __syncthreads();
        int excl = s - tsum + (wid > 0 ? warpsum[wid - 1] : 0) + carry;
        if (i0 + 0 < NN) g_rowstart[i0 + 0] = excl; excl += v0;
        if (i0 + 1 < NN) g_rowstart[i0 + 1] = excl; excl += v1;
        if (i0 + 2 < NN) g_rowstart[i0 + 2] = excl; excl += v2;
        if (i0 + 3 < NN) g_rowstart[i0 + 3] = excl;
        int total = warpsum[31];
        __syncthreads();
        if (tid == 0) carry += total;
        __syncthreads();
    }
    if (tid == 0) g_rowstart[NN] = carry;
}

__global__ void k_fill(const int* __restrict__ src, const int* __restrict__ dst, int E) {
    int e = blockIdx.x * blockDim.x + threadIdx.x;
    if (e >= E) return;
    int d = dst[e];
    int pos = atomicAdd(&g_cursor[d], 1);
    g_csr_src[g_rowstart[d] + pos] = src[e];
}

// ---------------- fused single-pass softmax + aggregation --------------------
// block per node (256 threads), warp per head, lane per output feature.
// No max-subtraction: |ea| <~ 16 so exp() is safe in fp32; out = acc/(sum+eps)
// equals the reference's per-edge normalization exactly.
__global__ void k_aggr(float* __restrict__ out) {
    const int n = blockIdx.x;
    const int head = threadIdx.x >> 5;
    const int lane = threadIdx.x & 31;
    __shared__ int s_rs, s_re;
    if (threadIdx.x == 0) {
        s_rs = g_rowstart[n];
        s_re = g_rowstart[n + 1];
    }
    __syncthreads();
    const int rs = s_rs, re = s_re;
    const float sd = g_sdst[n * HEADS_ + head];

    float acc = 0.f, wsum = 0.f;
    int i = rs;
    for (; i + 4 <= re; i += 4) {
        int s0 = g_csr_src[i + 0];
        int s1 = g_csr_src[i + 1];
        int s2 = g_csr_src[i + 2];
        int s3 = g_csr_src[i + 3];
        float a0 = g_ssrc[s0 * HEADS_ + head] + sd;
        float a1 = g_ssrc[s1 * HEADS_ + head] + sd;
        float a2 = g_ssrc[s2 * HEADS_ + head] + sd;
        float a3 = g_ssrc[s3 * HEADS_ + head] + sd;
        float h0 = g_h[(size_t)s0 * HF_ + head * OUTF_ + lane];
        float h1 = g_h[(size_t)s1 * HF_ + head * OUTF_ + lane];
        float h2 = g_h[(size_t)s2 * HF_ + head * OUTF_ + lane];
        float h3 = g_h[(size_t)s3 * HF_ + head * OUTF_ + lane];
        a0 = a0 > 0.f ? a0 : 0.2f * a0;
        a1 = a1 > 0.f ? a1 : 0.2f * a1;
        a2 = a2 > 0.f ? a2 : 0.2f * a2;
        a3 = a3 > 0.f ? a3 : 0.2f * a3;
        float e0 = __expf(a0);
        float e1 = __expf(a1);
        float e2 = __expf(a2);
        float e3 = __expf(a3);
        wsum += (e0 + e1) + (e2 + e3);
        acc = fmaf(e0, h0, acc);
        acc = fmaf(e1, h1, acc);
        acc = fmaf(e2, h2, acc);
        acc = fmaf(e3, h3, acc);
    }
    for (; i < re; i++) {
        int s = g_csr_src[i];
        float ea = g_ssrc[s * HEADS_ + head] + sd;
        ea = ea > 0.f ? ea : 0.2f * ea;
        float e = __expf(ea);
        wsum += e;
        acc = fmaf(e, g_h[(size_t)s * HF_ + head * OUTF_ + lane], acc);
    }
    out[(size_t)n * HF_ + head * OUTF_ + lane] = acc / (wsum + 1e-8f);
}

// ---------------- launch -----------------------------------------------------
extern "C" void kernel_launch(void* const* d_in, const int* in_sizes, int n_in,
                              void* d_out, int out_size) {
    const float* x     = (const float*)d_in[0];
    const int*   ei    = (const int*)d_in[1];
    const float* W     = (const float*)d_in[2];
    const float* a_src = (const float*)d_in[3];
    const float* a_dst = (const float*)d_in[4];
    float* out = (float*)d_out;

    const int M = in_sizes[0] / INF_;     // 50000
    const int E = in_sizes[1] / 2;        // 800000
    const int* src = ei;
    const int* dst = ei + E;

    const int mblocks = (M + 127) / 128;  // 391; mblocks*128 <= MPAD

    k_wsplit<<<(HF_ * INF_ + 255) / 256, 256>>>(W);
    k_wa<<<(HEADS_ * INF_ + 255) / 256, 256>>>(W, a_src, a_dst);
    k_xs<<<(MPAD * 32 + 255) / 256, 256>>>(x, M);
    k_gemm_wmma<<<dim3(2, mblocks), 256>>>();
    k_zero<<<(M + 255) / 256, 256>>>(M);
    k_count<<<(E + 255) / 256, 256>>>(dst, E);
    k_scan<<<1, 1024>>>(M);
    k_fill<<<(E + 255) / 256, 256>>>(src, dst, E);
    k_aggr<<<M, 256>>>(out);
}

// round 12
// speedup vs baseline: 1.4680x; 1.0869x over previous
#include <cuda_runtime.h>
#include <cuda_bf16.h>
#include <mma.h>
#include <cstdint>

using namespace nvcuda;

#define N_NODES 50000
#define E_EDGES 800000
#define INF_    256
#define OUTF_   32
#define HEADS_  8
#define HF_     256   // HEADS_ * OUTF_
#define MPAD    50048 // 391 * 128, padded row count for boundless stores

// ---------------- scratch (static __device__, no allocation) ----------------
__device__ __nv_bfloat16 g_wh[HF_ * INF_];               // W hi, [j=head*32+f][k]
__device__ __nv_bfloat16 g_wl[HF_ * INF_];               // W lo
__device__ float g_h[(size_t)MPAD * HF_];                // transformed features (padded)
__device__ float g_wasrc[HEADS_ * INF_];                 // W @ a_src  [h][k]
__device__ float g_wadst[HEADS_ * INF_];                 // W @ a_dst  [h][k]
__device__ float g_ssrc[N_NODES * HEADS_];
__device__ float g_sdst[N_NODES * HEADS_];
__device__ int   g_deg[N_NODES];
__device__ int   g_cursor[N_NODES];
__device__ int   g_rowstart[N_NODES + 1];
__device__ int   g_csr_src[E_EDGES];

// ---------------- W pack + bf16 split: [H,256,32] -> [j=256][k=256] ----------
__global__ void k_wsplit(const float* __restrict__ W) {
    int idx = blockIdx.x * blockDim.x + threadIdx.x;     // idx = j*256 + k
    if (idx >= HF_ * INF_) return;
    int j = idx >> 8;
    int k = idx & 255;
    int head = j >> 5;
    int f = j & 31;
    float w = W[head * (INF_ * OUTF_) + k * OUTF_ + f];
    __nv_bfloat16 hi = __float2bfloat16(w);
    float r = w - __bfloat162float(hi);
    g_wh[idx] = hi;
    g_wl[idx] = __float2bfloat16(r);
}

// ---------------- wa[h][k] = sum_f W[h][k][f] * a[h][f] ----------------------
__global__ void k_wa(const float* __restrict__ W,
                     const float* __restrict__ a_src,
                     const float* __restrict__ a_dst) {
    int t = blockIdx.x * blockDim.x + threadIdx.x;       // t = h*256 + k
    if (t >= HEADS_ * INF_) return;
    int h = t >> 8;
    int k = t & 255;
    const float* wp = W + h * (INF_ * OUTF_) + k * OUTF_;
    const float* as = a_src + h * OUTF_;
    const float* ad = a_dst + h * OUTF_;
    float ss = 0.f, sd = 0.f;
#pragma unroll
    for (int f = 0; f < OUTF_; f++) {
        float w = wp[f];
        ss = fmaf(w, as[f], ss);
        sd = fmaf(w, ad[f], sd);
    }
    g_wasrc[t] = ss;
    g_wadst[t] = sd;
}

// ---------------- attention logits: s = x . wa (warp per row) ----------------
__global__ void k_sc(const float* __restrict__ x, int M) {
    const int w = (blockIdx.x * blockDim.x + threadIdx.x) >> 5;
    const int lane = threadIdx.x & 31;
    if (w >= M) return;
    const size_t base = (size_t)w * INF_ + lane * 8;
    float4 v0 = *(const float4*)&x[base];
    float4 v1 = *(const float4*)&x[base + 4];
    float v[8] = {v0.x, v0.y, v0.z, v0.w, v1.x, v1.y, v1.z, v1.w};
    float ts[HEADS_], td[HEADS_];
#pragma unroll
    for (int h = 0; h < HEADS_; h++) {
        const float4* ws = (const float4*)&g_wasrc[h * INF_ + lane * 8];
        const float4* wd = (const float4*)&g_wadst[h * INF_ + lane * 8];
        float4 s0 = ws[0], s1 = ws[1], d0 = wd[0], d1 = wd[1];
        ts[h] = v[0] * s0.x + v[1] * s0.y + v[2] * s0.z + v[3] * s0.w +
                v[4] * s1.x + v[5] * s1.y + v[6] * s1.z + v[7] * s1.w;
        td[h] = v[0] * d0.x + v[1] * d0.y + v[2] * d0.z + v[3] * d0.w +
                v[4] * d1.x + v[5] * d1.y + v[6] * d1.z + v[7] * d1.w;
    }
#pragma unroll
    for (int off = 16; off; off >>= 1) {
#pragma unroll
        for (int h = 0; h < HEADS_; h++) {
            ts[h] += __shfl_xor_sync(0xffffffffu, ts[h], off);
            td[h] += __shfl_xor_sync(0xffffffffu, td[h], off);
        }
    }
    if (lane == 0) {
#pragma unroll
        for (int h = 0; h < HEADS_; h++) {
            g_ssrc[w * HEADS_ + h] = ts[h];
            g_sdst[w * HEADS_ + h] = td[h];
        }
    }
}

// ---------------- WMMA bf16-split GEMM (fused x-split, smem-staged) ----------
// CTA 128x128, 8 warps (4 row x 2 col), warp tile 32x64 = 2x4 m16n16k16 frags.
// acc += ah*bh + ah*bl + al*bh  (al*bl ~2^-18 dropped). x split fp32->hi/lo in
// registers during the smem stage; stores go unguarded into padded g_h.
#define LDA 40   // padded smem leading dim (elements); conflict-free for LDSM
__global__ void __launch_bounds__(256, 2) k_gemm_wmma(const float* __restrict__ x, int M) {
    __shared__ __nv_bfloat16 Ah[128 * LDA], Al[128 * LDA];
    __shared__ __nv_bfloat16 Bh[128 * LDA], Bl[128 * LDA];
    const int tid = threadIdx.x;
    const int warp = tid >> 5;
    const int wm = warp & 3;
    const int wn = warp >> 2;
    const int m0 = blockIdx.y * 128;
    const int n0 = blockIdx.x * 128;

    wmma::fragment<wmma::accumulator, 16, 16, 16, float> acc[2][4];
#pragma unroll
    for (int i = 0; i < 2; i++)
#pragma unroll
        for (int j = 0; j < 4; j++) wmma::fill_fragment(acc[i][j], 0.f);

    for (int k0 = 0; k0 < INF_; k0 += 32) {
        __syncthreads();
#pragma unroll
        for (int u = 0; u < 2; u++) {
            int id = tid + u * 256;          // 0..511
            int row = id >> 2;               // 0..127
            int c8 = (id & 3) * 8;           // col in elements
            // A: load fp32 x, split to bf16 hi/lo in-register
            float4 v0 = make_float4(0.f, 0.f, 0.f, 0.f), v1 = v0;
            if (m0 + row < M) {
                const float* xp = &x[(size_t)(m0 + row) * INF_ + k0 + c8];
                v0 = *(const float4*)xp;
                v1 = *(const float4*)(xp + 4);
            }
            float v[8] = {v0.x, v0.y, v0.z, v0.w, v1.x, v1.y, v1.z, v1.w};
            uint32_t hp[4], lp[4];
#pragma unroll
            for (int q = 0; q < 4; q++) {
                __nv_bfloat16 h0 = __float2bfloat16(v[2 * q]);
                __nv_bfloat16 h1 = __float2bfloat16(v[2 * q + 1]);
                float r0 = v[2 * q] - __bfloat162float(h0);
                float r1 = v[2 * q + 1] - __bfloat162float(h1);
                hp[q] = (uint32_t)__bfloat16_as_ushort(h0) |
                        ((uint32_t)__bfloat16_as_ushort(h1) << 16);
                lp[q] = (uint32_t)__bfloat16_as_ushort(__float2bfloat16(r0)) |
                        ((uint32_t)__bfloat16_as_ushort(__float2bfloat16(r1)) << 16);
            }
            *(uint4*)&Ah[row * LDA + c8] = make_uint4(hp[0], hp[1], hp[2], hp[3]);
            *(uint4*)&Al[row * LDA + c8] = make_uint4(lp[0], lp[1], lp[2], lp[3]);
            // B: straight bf16 copy (pre-split)
            size_t gb = (size_t)(n0 + row) * INF_ + k0 + c8;
            *(uint4*)&Bh[row * LDA + c8] = *(const uint4*)&g_wh[gb];
            *(uint4*)&Bl[row * LDA + c8] = *(const uint4*)&g_wl[gb];
        }
        __syncthreads();

#pragma unroll
        for (int ks = 0; ks < 2; ks++) {
            wmma::fragment<wmma::matrix_a, 16, 16, 16, __nv_bfloat16, wmma::row_major> ah[2], al[2];
#pragma unroll
            for (int i = 0; i < 2; i++) {
                int ro = (wm * 32 + i * 16) * LDA + ks * 16;
                wmma::load_matrix_sync(ah[i], &Ah[ro], LDA);
                wmma::load_matrix_sync(al[i], &Al[ro], LDA);
            }
#pragma unroll
            for (int j = 0; j < 4; j++) {
                wmma::fragment<wmma::matrix_b, 16, 16, 16, __nv_bfloat16, wmma::col_major> bh, bl;
                int ro = (wn * 64 + j * 16) * LDA + ks * 16;
                wmma::load_matrix_sync(bh, &Bh[ro], LDA);
                wmma::load_matrix_sync(bl, &Bl[ro], LDA);
#pragma unroll
                for (int i = 0; i < 2; i++) {
                    wmma::mma_sync(acc[i][j], ah[i], bh, acc[i][j]);
                    wmma::mma_sync(acc[i][j], ah[i], bl, acc[i][j]);
                    wmma::mma_sync(acc[i][j], al[i], bh, acc[i][j]);
                }
            }
        }
    }

    // stores unguarded into padded g_h (MPAD rows)
#pragma unroll
    for (int i = 0; i < 2; i++)
#pragma unroll
        for (int j = 0; j < 4; j++)
            wmma::store_matrix_sync(
                &g_h[(size_t)(m0 + wm * 32 + 16 * i) * HF_ + n0 + wn * 64 + 16 * j],
                acc[i][j], HF_, wmma::mem_row_major);
}

// ---------------- CSR build --------------------------------------------------
__global__ void k_zero(int NN) {
    int t = blockIdx.x * blockDim.x + threadIdx.x;
    if (t < NN) { g_deg[t] = 0; g_cursor[t] = 0; }
}

__global__ void k_count(const int* __restrict__ dst, int E) {
    int e = blockIdx.x * blockDim.x + threadIdx.x;
    if (e < E) atomicAdd(&g_deg[dst[e]], 1);
}

// single-block shfl scan, 4 elements per thread -> g_rowstart
__global__ void k_scan(int NN) {
    __shared__ int warpsum[32];
    __shared__ int carry;
    const int tid = threadIdx.x;
    const int lane = tid & 31;
    const int wid = tid >> 5;
    if (tid == 0) carry = 0;
    __syncthreads();
    for (int base = 0; base < NN; base += 4096) {
        int i0 = base + tid * 4;
        int v0 = (i0 + 0 < NN) ? g_deg[i0 + 0] : 0;
        int v1 = (i0 + 1 < NN) ? g_deg[i0 + 1] : 0;
        int v2 = (i0 + 2 < NN) ? g_deg[i0 + 2] : 0;
        int v3 = (i0 + 3 < NN) ? g_deg[i0 + 3] : 0;
        int tsum = v0 + v1 + v2 + v3;
        int s = tsum;
#pragma unroll
        for (int o = 1; o < 32; o <<= 1) {
            int t = __shfl_up_sync(0xffffffffu, s, o);
            if (lane >= o) s += t;
        }
        if (lane == 31) warpsum[wid] = s;
        __syncthreads();
        if (wid == 0) {
            int ws = warpsum[lane];
#pragma unroll
            for (int o = 1; o < 32; o <<= 1) {
                int t = __shfl_up_sync(0xffffffffu, ws, o);
                if (lane >= o) ws += t;
            }
            warpsum[lane] = ws;
        }
        __syncthreads();
        int excl = s - tsum + (wid > 0 ? warpsum[wid - 1] : 0) + carry;
        if (i0 + 0 < NN) g_rowstart[i0 + 0] = excl; excl += v0;
        if (i0 + 1 < NN) g_rowstart[i0 + 1] = excl; excl += v1;
        if (i0 + 2 < NN) g_rowstart[i0 + 2] = excl; excl += v2;
        if (i0 + 3 < NN) g_rowstart[i0 + 3] = excl;
        int total = warpsum[31];
        __syncthreads();
        if (tid == 0) carry += total;
        __syncthreads();
    }
    if (tid == 0) g_rowstart[NN] = carry;
}

__global__ void k_fill(const int* __restrict__ src, const int* __restrict__ dst, int E) {
    int e = blockIdx.x * blockDim.x + threadIdx.x;
    if (e >= E) return;
    int d = dst[e];
    int pos = atomicAdd(&g_cursor[d], 1);
    g_csr_src[g_rowstart[d] + pos] = src[e];
}

// ---------------- fused single-pass softmax + aggregation --------------------
// block per node (256 threads), warp per head, lane per output feature.
// No max-subtraction: |ea| <~ 16 so exp() is safe in fp32; out = acc/(sum+eps)
// equals the reference's per-edge normalization.
__global__ void k_aggr(float* __restrict__ out) {
    const int n = blockIdx.x;
    const int head = threadIdx.x >> 5;
    const int lane = threadIdx.x & 31;
    __shared__ int s_rs, s_re;
    if (threadIdx.x == 0) {
        s_rs = g_rowstart[n];
        s_re = g_rowstart[n + 1];
    }
    __syncthreads();
    const int rs = s_rs, re = s_re;
    const float sd = g_sdst[n * HEADS_ + head];

    float acc = 0.f, wsum = 0.f;
    int i = rs;
    for (; i + 8 <= re; i += 8) {
        int sn[8];
        float an[8], hn[8];
#pragma unroll
        for (int q = 0; q < 8; q++) sn[q] = g_csr_src[i + q];
#pragma unroll
        for (int q = 0; q < 8; q++) an[q] = g_ssrc[sn[q] * HEADS_ + head] + sd;
#pragma unroll
        for (int q = 0; q < 8; q++) hn[q] = g_h[(size_t)sn[q] * HF_ + head * OUTF_ + lane];
#pragma unroll
        for (int q = 0; q < 8; q++) {
            float a = an[q];
            a = a > 0.f ? a : 0.2f * a;
            float e = __expf(a);
            wsum += e;
            acc = fmaf(e, hn[q], acc);
        }
    }
    for (; i < re; i++) {
        int s = g_csr_src[i];
        float ea = g_ssrc[s * HEADS_ + head] + sd;
        ea = ea > 0.f ? ea : 0.2f * ea;
        float e = __expf(ea);
        wsum += e;
        acc = fmaf(e, g_h[(size_t)s * HF_ + head * OUTF_ + lane], acc);
    }
    out[(size_t)n * HF_ + head * OUTF_ + lane] = acc / (wsum + 1e-8f);
}

// ---------------- launch -----------------------------------------------------
extern "C" void kernel_launch(void* const* d_in, const int* in_sizes, int n_in,
                              void* d_out, int out_size) {
    const float* x     = (const float*)d_in[0];
    const int*   ei    = (const int*)d_in[1];
    const float* W     = (const float*)d_in[2];
    const float* a_src = (const float*)d_in[3];
    const float* a_dst = (const float*)d_in[4];
    float* out = (float*)d_out;

    const int M = in_sizes[0] / INF_;     // 50000
    const int E = in_sizes[1] / 2;        // 800000
    const int* src = ei;
    const int* dst = ei + E;

    const int mblocks = (M + 127) / 128;  // 391; mblocks*128 <= MPAD

    k_wsplit<<<(HF_ * INF_ + 255) / 256, 256>>>(W);
    k_wa<<<(HEADS_ * INF_ + 255) / 256, 256>>>(W, a_src, a_dst);
    k_gemm_wmma<<<dim3(2, mblocks), 256>>>(x, M);
    k_sc<<<(M * 32 + 255) / 256, 256>>>(x, M);
    k_zero<<<(M + 255) / 256, 256>>>(M);
    k_count<<<(E + 255) / 256, 256>>>(dst, E);
    k_scan<<<1, 1024>>>(M);
    k_fill<<<(E + 255) / 256, 256>>>(src, dst, E);
    k_aggr<<<M, 256>>>(out);
}

// round 13
// speedup vs baseline: 1.5355x; 1.0460x over previous
#include <cuda_runtime.h>
#include <cuda_bf16.h>
#include <mma.h>
#include <cstdint>

using namespace nvcuda;

#define N_NODES 50000
#define E_EDGES 800000
#define INF_    256
#define OUTF_   32
#define HEADS_  8
#define HF_     256   // HEADS_ * OUTF_
#define MPAD    50048 // 391 * 128, padded row count for boundless stores

// ---------------- scratch (static __device__, no allocation) ----------------
__device__ __nv_bfloat16 g_wh[HF_ * INF_];               // W hi, [j=head*32+f][k]
__device__ __nv_bfloat16 g_wl[HF_ * INF_];               // W lo
__device__ float g_h[(size_t)MPAD * HF_];                // transformed features (padded)
__device__ float g_wasrc[HEADS_ * INF_];                 // W @ a_src  [h][k]
__device__ float g_wadst[HEADS_ * INF_];                 // W @ a_dst  [h][k]
__device__ float g_ssrc[N_NODES * HEADS_];
__device__ float g_sdst[N_NODES * HEADS_];
__device__ int   g_deg[N_NODES];
__device__ int   g_cursor[N_NODES];
__device__ int   g_rowstart[N_NODES + 1];
__device__ int   g_csr_src[E_EDGES];

// ---------------- W pack + bf16 split: [H,256,32] -> [j=256][k=256] ----------
__global__ void k_wsplit(const float* __restrict__ W) {
    int idx = blockIdx.x * blockDim.x + threadIdx.x;     // idx = j*256 + k
    if (idx >= HF_ * INF_) return;
    int j = idx >> 8;
    int k = idx & 255;
    int head = j >> 5;
    int f = j & 31;
    float w = W[head * (INF_ * OUTF_) + k * OUTF_ + f];
    __nv_bfloat16 hi = __float2bfloat16(w);
    float r = w - __bfloat162float(hi);
    g_wh[idx] = hi;
    g_wl[idx] = __float2bfloat16(r);
}

// ---------------- wa[h][k] = sum_f W[h][k][f] * a[h][f] ----------------------
__global__ void k_wa(const float* __restrict__ W,
                     const float* __restrict__ a_src,
                     const float* __restrict__ a_dst) {
    int t = blockIdx.x * blockDim.x + threadIdx.x;       // t = h*256 + k
    if (t >= HEADS_ * INF_) return;
    int h = t >> 8;
    int k = t & 255;
    const float* wp = W + h * (INF_ * OUTF_) + k * OUTF_;
    const float* as = a_src + h * OUTF_;
    const float* ad = a_dst + h * OUTF_;
    float ss = 0.f, sd = 0.f;
#pragma unroll
    for (int f = 0; f < OUTF_; f++) {
        float w = wp[f];
        ss = fmaf(w, as[f], ss);
        sd = fmaf(w, ad[f], sd);
    }
    g_wasrc[t] = ss;
    g_wadst[t] = sd;
}

// ---------------- attention logits: s = x . wa (warp per 4 rows) -------------
// wa fragments loaded once per head and reused across 4 rows: L1 wavefronts
// drop from ~136/row to ~40/row.
__global__ void k_sc(const float* __restrict__ x, int M) {
    const int w = (blockIdx.x * blockDim.x + threadIdx.x) >> 5;  // warp id
    const int lane = threadIdx.x & 31;
    const int r0 = w * 4;
    if (r0 >= M) return;

    float v[4][8];
#pragma unroll
    for (int r = 0; r < 4; r++) {
        int rr = r0 + r; if (rr > M - 1) rr = M - 1;
        const size_t base = (size_t)rr * INF_ + lane * 8;
        float4 a = *(const float4*)&x[base];
        float4 b = *(const float4*)&x[base + 4];
        v[r][0] = a.x; v[r][1] = a.y; v[r][2] = a.z; v[r][3] = a.w;
        v[r][4] = b.x; v[r][5] = b.y; v[r][6] = b.z; v[r][7] = b.w;
    }
#pragma unroll
    for (int h = 0; h < HEADS_; h++) {
        const float4* wsp = (const float4*)&g_wasrc[h * INF_ + lane * 8];
        const float4* wdp = (const float4*)&g_wadst[h * INF_ + lane * 8];
        float4 s0 = wsp[0], s1 = wsp[1], d0 = wdp[0], d1 = wdp[1];
        float ws[8] = {s0.x, s0.y, s0.z, s0.w, s1.x, s1.y, s1.z, s1.w};
        float wd[8] = {d0.x, d0.y, d0.z, d0.w, d1.x, d1.y, d1.z, d1.w};
#pragma unroll
        for (int r = 0; r < 4; r++) {
            float ts = 0.f, td = 0.f;
#pragma unroll
            for (int q = 0; q < 8; q++) {
                ts = fmaf(v[r][q], ws[q], ts);
                td = fmaf(v[r][q], wd[q], td);
            }
#pragma unroll
            for (int off = 16; off; off >>= 1) {
                ts += __shfl_xor_sync(0xffffffffu, ts, off);
                td += __shfl_xor_sync(0xffffffffu, td, off);
            }
            if (lane == 0 && r0 + r < M) {
                g_ssrc[(r0 + r) * HEADS_ + h] = ts;
                g_sdst[(r0 + r) * HEADS_ + h] = td;
            }
        }
    }
}

// ---------------- WMMA bf16-split GEMM (fused x-split, smem-staged) ----------
// CTA 128x128, 8 warps (4 row x 2 col), warp tile 32x64 = 2x4 m16n16k16 frags.
// acc += ah*bh + ah*bl + al*bh  (al*bl ~2^-18 dropped). x split fp32->hi/lo in
// registers during the smem stage; stores go unguarded into padded g_h.
#define LDA 40   // padded smem leading dim (elements); conflict-free for LDSM
__global__ void __launch_bounds__(256, 2) k_gemm_wmma(const float* __restrict__ x, int M) {
    __shared__ __nv_bfloat16 Ah[128 * LDA], Al[128 * LDA];
    __shared__ __nv_bfloat16 Bh[128 * LDA], Bl[128 * LDA];
    const int tid = threadIdx.x;
    const int warp = tid >> 5;
    const int wm = warp & 3;
    const int wn = warp >> 2;
    const int m0 = blockIdx.y * 128;
    const int n0 = blockIdx.x * 128;

    wmma::fragment<wmma::accumulator, 16, 16, 16, float> acc[2][4];
#pragma unroll
    for (int i = 0; i < 2; i++)
#pragma unroll
        for (int j = 0; j < 4; j++) wmma::fill_fragment(acc[i][j], 0.f);

    for (int k0 = 0; k0 < INF_; k0 += 32) {
        __syncthreads();
#pragma unroll
        for (int u = 0; u < 2; u++) {
            int id = tid + u * 256;          // 0..511
            int row = id >> 2;               // 0..127
            int c8 = (id & 3) * 8;           // col in elements
            // A: load fp32 x, split to bf16 hi/lo in-register
            float4 v0 = make_float4(0.f, 0.f, 0.f, 0.f), v1 = v0;
            if (m0 + row < M) {
                const float* xp = &x[(size_t)(m0 + row) * INF_ + k0 + c8];
                v0 = *(const float4*)xp;
                v1 = *(const float4*)(xp + 4);
            }
            float v[8] = {v0.x, v0.y, v0.z, v0.w, v1.x, v1.y, v1.z, v1.w};
            uint32_t hp[4], lp[4];
#pragma unroll
            for (int q = 0; q < 4; q++) {
                __nv_bfloat16 h0 = __float2bfloat16(v[2 * q]);
                __nv_bfloat16 h1 = __float2bfloat16(v[2 * q + 1]);
                float r0 = v[2 * q] - __bfloat162float(h0);
                float r1 = v[2 * q + 1] - __bfloat162float(h1);
                hp[q] = (uint32_t)__bfloat16_as_ushort(h0) |
                        ((uint32_t)__bfloat16_as_ushort(h1) << 16);
                lp[q] = (uint32_t)__bfloat16_as_ushort(__float2bfloat16(r0)) |
                        ((uint32_t)__bfloat16_as_ushort(__float2bfloat16(r1)) << 16);
            }
            *(uint4*)&Ah[row * LDA + c8] = make_uint4(hp[0], hp[1], hp[2], hp[3]);
            *(uint4*)&Al[row * LDA + c8] = make_uint4(lp[0], lp[1], lp[2], lp[3]);
            // B: straight bf16 copy (pre-split)
            size_t gb = (size_t)(n0 + row) * INF_ + k0 + c8;
            *(uint4*)&Bh[row * LDA + c8] = *(const uint4*)&g_wh[gb];
            *(uint4*)&Bl[row * LDA + c8] = *(const uint4*)&g_wl[gb];
        }
        __syncthreads();

#pragma unroll
        for (int ks = 0; ks < 2; ks++) {
            wmma::fragment<wmma::matrix_a, 16, 16, 16, __nv_bfloat16, wmma::row_major> ah[2], al[2];
#pragma unroll
            for (int i = 0; i < 2; i++) {
                int ro = (wm * 32 + i * 16) * LDA + ks * 16;
                wmma::load_matrix_sync(ah[i], &Ah[ro], LDA);
                wmma::load_matrix_sync(al[i], &Al[ro], LDA);
            }
#pragma unroll
            for (int j = 0; j < 4; j++) {
                wmma::fragment<wmma::matrix_b, 16, 16, 16, __nv_bfloat16, wmma::col_major> bh, bl;
                int ro = (wn * 64 + j * 16) * LDA + ks * 16;
                wmma::load_matrix_sync(bh, &Bh[ro], LDA);
                wmma::load_matrix_sync(bl, &Bl[ro], LDA);
#pragma unroll
                for (int i = 0; i < 2; i++) {
                    wmma::mma_sync(acc[i][j], ah[i], bh, acc[i][j]);
                    wmma::mma_sync(acc[i][j], ah[i], bl, acc[i][j]);
                    wmma::mma_sync(acc[i][j], al[i], bh, acc[i][j]);
                }
            }
        }
    }

    // stores unguarded into padded g_h (MPAD rows)
#pragma unroll
    for (int i = 0; i < 2; i++)
#pragma unroll
        for (int j = 0; j < 4; j++)
            wmma::store_matrix_sync(
                &g_h[(size_t)(m0 + wm * 32 + 16 * i) * HF_ + n0 + wn * 64 + 16 * j],
                acc[i][j], HF_, wmma::mem_row_major);
}

// ---------------- CSR build --------------------------------------------------
__global__ void k_zero(int NN) {
    int t = blockIdx.x * blockDim.x + threadIdx.x;
    if (t < NN) { g_deg[t] = 0; g_cursor[t] = 0; }
}

__global__ void k_count(const int* __restrict__ dst, int E) {
    int e = blockIdx.x * blockDim.x + threadIdx.x;
    if (e < E) atomicAdd(&g_deg[dst[e]], 1);
}

// single-block shfl scan, 4 elements per thread -> g_rowstart
__global__ void k_scan(int NN) {
    __shared__ int warpsum[32];
    __shared__ int carry;
    const int tid = threadIdx.x;
    const int lane = tid & 31;
    const int wid = tid >> 5;
    if (tid == 0) carry = 0;
    __syncthreads();
    for (int base = 0; base < NN; base += 4096) {
        int i0 = base + tid * 4;
        int v0 = (i0 + 0 < NN) ? g_deg[i0 + 0] : 0;
        int v1 = (i0 + 1 < NN) ? g_deg[i0 + 1] : 0;
        int v2 = (i0 + 2 < NN) ? g_deg[i0 + 2] : 0;
        int v3 = (i0 + 3 < NN) ? g_deg[i0 + 3] : 0;
        int tsum = v0 + v1 + v2 + v3;
        int s = tsum;
#pragma unroll
        for (int o = 1; o < 32; o <<= 1) {
            int t = __shfl_up_sync(0xffffffffu, s, o);
            if (lane >= o) s += t;
        }
        if (lane == 31) warpsum[wid] = s;
        __syncthreads();
        if (wid == 0) {
            int ws = warpsum[lane];
#pragma unroll
            for (int o = 1; o < 32; o <<= 1) {
                int t = __shfl_up_sync(0xffffffffu, ws, o);
                if (lane >= o) ws += t;
            }
            warpsum[lane] = ws;
        }
        __syncthreads();
        int excl = s - tsum + (wid > 0 ? warpsum[wid - 1] : 0) + carry;
        if (i0 + 0 < NN) g_rowstart[i0 + 0] = excl; excl += v0;
        if (i0 + 1 < NN) g_rowstart[i0 + 1] = excl; excl += v1;
        if (i0 + 2 < NN) g_rowstart[i0 + 2] = excl; excl += v2;
        if (i0 + 3 < NN) g_rowstart[i0 + 3] = excl;
        int total = warpsum[31];
        __syncthreads();
        if (tid == 0) carry += total;
        __syncthreads();
    }
    if (tid == 0) g_rowstart[NN] = carry;
}

__global__ void k_fill(const int* __restrict__ src, const int* __restrict__ dst, int E) {
    int e = blockIdx.x * blockDim.x + threadIdx.x;
    if (e >= E) return;
    int d = dst[e];
    int pos = atomicAdd(&g_cursor[d], 1);
    g_csr_src[g_rowstart[d] + pos] = src[e];
}

// ---------------- fused single-pass softmax + aggregation --------------------
// 2 nodes per 512-thread block, warp per (node,head), lane per output feature.
// No max-subtraction: |ea| <~ 16 so exp() is safe in fp32; out = acc/(sum+eps)
// equals the reference's per-edge normalization.
__global__ void __launch_bounds__(512) k_aggr(float* __restrict__ out, int NN) {
    const int n = blockIdx.x * 2 + (threadIdx.x >> 8);
    if (n >= NN) return;
    const int head = (threadIdx.x >> 5) & 7;
    const int lane = threadIdx.x & 31;
    const int rs = g_rowstart[n];
    const int re = g_rowstart[n + 1];
    const float sd = g_sdst[n * HEADS_ + head];

    float acc = 0.f, wsum = 0.f;
    int i = rs;
    for (; i + 8 <= re; i += 8) {
        int sn[8];
        float an[8], hn[8];
#pragma unroll
        for (int q = 0; q < 8; q++) sn[q] = g_csr_src[i + q];
#pragma unroll
        for (int q = 0; q < 8; q++) an[q] = g_ssrc[sn[q] * HEADS_ + head] + sd;
#pragma unroll
        for (int q = 0; q < 8; q++) hn[q] = g_h[(size_t)sn[q] * HF_ + head * OUTF_ + lane];
#pragma unroll
        for (int q = 0; q < 8; q++) {
            float a = an[q];
            a = a > 0.f ? a : 0.2f * a;
            float e = __expf(a);
            wsum += e;
            acc = fmaf(e, hn[q], acc);
        }
    }
    for (; i < re; i++) {
        int s = g_csr_src[i];
        float ea = g_ssrc[s * HEADS_ + head] + sd;
        ea = ea > 0.f ? ea : 0.2f * ea;
        float e = __expf(ea);
        wsum += e;
        acc = fmaf(e, g_h[(size_t)s * HF_ + head * OUTF_ + lane], acc);
    }
    out[(size_t)n * HF_ + head * OUTF_ + lane] = acc / (wsum + 1e-8f);
}

// ---------------- launch -----------------------------------------------------
extern "C" void kernel_launch(void* const* d_in, const int* in_sizes, int n_in,
                              void* d_out, int out_size) {
    const float* x     = (const float*)d_in[0];
    const int*   ei    = (const int*)d_in[1];
    const float* W     = (const float*)d_in[2];
    const float* a_src = (const float*)d_in[3];
    const float* a_dst = (const float*)d_in[4];
    float* out = (float*)d_out;

    const int M = in_sizes[0] / INF_;     // 50000
    const int E = in_sizes[1] / 2;        // 800000
    const int* src = ei;
    const int* dst = ei + E;

    const int mblocks = (M + 127) / 128;  // 391; mblocks*128 <= MPAD
    const int scwarps = (M + 3) / 4;      // 4 rows per warp

    k_wsplit<<<(HF_ * INF_ + 255) / 256, 256>>>(W);
    k_wa<<<(HEADS_ * INF_ + 255) / 256, 256>>>(W, a_src, a_dst);
    k_gemm_wmma<<<dim3(2, mblocks), 256>>>(x, M);
    k_sc<<<(scwarps * 32 + 255) / 256, 256>>>(x, M);
    k_zero<<<(M + 255) / 256, 256>>>(M);
    k_count<<<(E + 255) / 256, 256>>>(dst, E);
    k_scan<<<1, 1024>>>(M);
    k_fill<<<(E + 255) / 256, 256>>>(src, dst, E);
    k_aggr<<<(M + 1) / 2, 512>>>(out, M);
}

// round 14
// speedup vs baseline: 1.6518x; 1.0757x over previous
#include <cuda_runtime.h>
#include <cuda_bf16.h>
#include <mma.h>
#include <cstdint>

using namespace nvcuda;

#define N_NODES 50000
#define E_EDGES 800000
#define INF_    256
#define OUTF_   32
#define HEADS_  8
#define HF_     256   // HEADS_ * OUTF_
#define MPAD    50048 // 391 * 128, padded row count for boundless stores

// ---------------- scratch (static __device__, no allocation) ----------------
__device__ __nv_bfloat16 g_wh[HF_ * INF_];               // W hi, [j=head*32+f][k]
__device__ __nv_bfloat16 g_wl[HF_ * INF_];               // W lo
__device__ float g_h[(size_t)MPAD * HF_];                // transformed features (padded)
__device__ float g_ssrc[N_NODES * HEADS_];
__device__ float g_sdst[N_NODES * HEADS_];
__device__ int   g_deg[N_NODES];
__device__ int   g_cursor[N_NODES];
__device__ int   g_rowstart[N_NODES + 1];
__device__ int   g_csr_src[E_EDGES];

// ---------------- W pack + bf16 split: [H,256,32] -> [j=256][k=256] ----------
__global__ void k_wsplit(const float* __restrict__ W) {
    int idx = blockIdx.x * blockDim.x + threadIdx.x;     // idx = j*256 + k
    if (idx >= HF_ * INF_) return;
    int j = idx >> 8;
    int k = idx & 255;
    int head = j >> 5;
    int f = j & 31;
    float w = W[head * (INF_ * OUTF_) + k * OUTF_ + f];
    __nv_bfloat16 hi = __float2bfloat16(w);
    float r = w - __bfloat162float(hi);
    g_wh[idx] = hi;
    g_wl[idx] = __float2bfloat16(r);
}

// ---------------- WMMA bf16-split GEMM + fused score epilogue ----------------
// CTA 128x128, 8 warps (4 row x 2 col), warp tile 32x64 = 2x4 m16n16k16 frags.
// acc += ah*bh + ah*bl + al*bh  (al*bl ~2^-18 dropped). x split fp32->hi/lo in
// registers during the smem stage; h stores go unguarded into padded g_h.
// Epilogue: s_src/s_dst computed from the CTA's just-stored h rows (L1-hot),
// one thread per (row, 2-head half) -> no cross-lane reductions.
#define LDA 40   // padded smem leading dim (elements); conflict-free for LDSM
__global__ void __launch_bounds__(256, 2) k_gemm_wmma(const float* __restrict__ x,
                                                      const float* __restrict__ a_src,
                                                      const float* __restrict__ a_dst,
                                                      int M) {
    __shared__ __nv_bfloat16 Ah[128 * LDA], Al[128 * LDA];
    __shared__ __nv_bfloat16 Bh[128 * LDA], Bl[128 * LDA];
    const int tid = threadIdx.x;
    const int warp = tid >> 5;
    const int wm = warp & 3;
    const int wn = warp >> 2;
    const int m0 = blockIdx.y * 128;
    const int n0 = blockIdx.x * 128;

    wmma::fragment<wmma::accumulator, 16, 16, 16, float> acc[2][4];
#pragma unroll
    for (int i = 0; i < 2; i++)
#pragma unroll
        for (int j = 0; j < 4; j++) wmma::fill_fragment(acc[i][j], 0.f);

    for (int k0 = 0; k0 < INF_; k0 += 32) {
        __syncthreads();
#pragma unroll
        for (int u = 0; u < 2; u++) {
            int id = tid + u * 256;          // 0..511
            int row = id >> 2;               // 0..127
            int c8 = (id & 3) * 8;           // col in elements
            // A: load fp32 x, split to bf16 hi/lo in-register
            float4 v0 = make_float4(0.f, 0.f, 0.f, 0.f), v1 = v0;
            if (m0 + row < M) {
                const float* xp = &x[(size_t)(m0 + row) * INF_ + k0 + c8];
                v0 = *(const float4*)xp;
                v1 = *(const float4*)(xp + 4);
            }
            float v[8] = {v0.x, v0.y, v0.z, v0.w, v1.x, v1.y, v1.z, v1.w};
            uint32_t hp[4], lp[4];
#pragma unroll
            for (int q = 0; q < 4; q++) {
                __nv_bfloat16 h0 = __float2bfloat16(v[2 * q]);
                __nv_bfloat16 h1 = __float2bfloat16(v[2 * q + 1]);
                float r0 = v[2 * q] - __bfloat162float(h0);
                float r1 = v[2 * q + 1] - __bfloat162float(h1);
                hp[q] = (uint32_t)__bfloat16_as_ushort(h0) |
                        ((uint32_t)__bfloat16_as_ushort(h1) << 16);
                lp[q] = (uint32_t)__bfloat16_as_ushort(__float2bfloat16(r0)) |
                        ((uint32_t)__bfloat16_as_ushort(__float2bfloat16(r1)) << 16);
            }
            *(uint4*)&Ah[row * LDA + c8] = make_uint4(hp[0], hp[1], hp[2], hp[3]);
            *(uint4*)&Al[row * LDA + c8] = make_uint4(lp[0], lp[1], lp[2], lp[3]);
            // B: straight bf16 copy (pre-split)
            size_t gb = (size_t)(n0 + row) * INF_ + k0 + c8;
            *(uint4*)&Bh[row * LDA + c8] = *(const uint4*)&g_wh[gb];
            *(uint4*)&Bl[row * LDA + c8] = *(const uint4*)&g_wl[gb];
        }
        __syncthreads();

#pragma unroll
        for (int ks = 0; ks < 2; ks++) {
            wmma::fragment<wmma::matrix_a, 16, 16, 16, __nv_bfloat16, wmma::row_major> ah[2], al[2];
#pragma unroll
            for (int i = 0; i < 2; i++) {
                int ro = (wm * 32 + i * 16) * LDA + ks * 16;
                wmma::load_matrix_sync(ah[i], &Ah[ro], LDA);
                wmma::load_matrix_sync(al[i], &Al[ro], LDA);
            }
#pragma unroll
            for (int j = 0; j < 4; j++) {
                wmma::fragment<wmma::matrix_b, 16, 16, 16, __nv_bfloat16, wmma::col_major> bh, bl;
                int ro = (wn * 64 + j * 16) * LDA + ks * 16;
                wmma::load_matrix_sync(bh, &Bh[ro], LDA);
                wmma::load_matrix_sync(bl, &Bl[ro], LDA);
#pragma unroll
                for (int i = 0; i < 2; i++) {
                    wmma::mma_sync(acc[i][j], ah[i], bh, acc[i][j]);
                    wmma::mma_sync(acc[i][j], ah[i], bl, acc[i][j]);
                    wmma::mma_sync(acc[i][j], al[i], bh, acc[i][j]);
                }
            }
        }
    }

    // stores unguarded into padded g_h (MPAD rows)
#pragma unroll
    for (int i = 0; i < 2; i++)
#pragma unroll
        for (int j = 0; j < 4; j++)
            wmma::store_matrix_sync(
                &g_h[(size_t)(m0 + wm * 32 + 16 * i) * HF_ + n0 + wn * 64 + 16 * j],
                acc[i][j], HF_, wmma::mem_row_major);

    // ---- fused score epilogue: block-scope visibility of our own g_h stores
    __syncthreads();
    {
        const int r = tid >> 1;               // 0..127
        const int half = tid & 1;             // 0..1
        const int row = m0 + r;
        if (row < M) {
            const int c0 = n0 + half * 64;    // 2 heads' columns
            const int hbase = c0 >> 5;        // first head index
            const float* hp = &g_h[(size_t)row * HF_ + c0];
            float s0 = 0.f, d0 = 0.f, s1 = 0.f, d1 = 0.f;
#pragma unroll
            for (int q = 0; q < 8; q++) {
                float4 hv0 = *(const float4*)&hp[q * 4];
                float4 hv1 = *(const float4*)&hp[32 + q * 4];
                float4 a0 = *(const float4*)&a_src[hbase * 32 + q * 4];
                float4 b0 = *(const float4*)&a_dst[hbase * 32 + q * 4];
                float4 a1 = *(const float4*)&a_src[(hbase + 1) * 32 + q * 4];
                float4 b1 = *(const float4*)&a_dst[(hbase + 1) * 32 + q * 4];
                s0 += hv0.x * a0.x + hv0.y * a0.y + hv0.z * a0.z + hv0.w * a0.w;
                d0 += hv0.x * b0.x + hv0.y * b0.y + hv0.z * b0.z + hv0.w * b0.w;
                s1 += hv1.x * a1.x + hv1.y * a1.y + hv1.z * a1.z + hv1.w * a1.w;
                d1 += hv1.x * b1.x + hv1.y * b1.y + hv1.z * b1.z + hv1.w * b1.w;
            }
            g_ssrc[row * HEADS_ + hbase] = s0;
            g_ssrc[row * HEADS_ + hbase + 1] = s1;
            g_sdst[row * HEADS_ + hbase] = d0;
            g_sdst[row * HEADS_ + hbase + 1] = d1;
        }
    }
}

// ---------------- CSR build --------------------------------------------------
__global__ void k_zero(int NN) {
    int t = blockIdx.x * blockDim.x + threadIdx.x;
    if (t < NN) { g_deg[t] = 0; g_cursor[t] = 0; }
}

__global__ void k_count(const int* __restrict__ dst, int E) {
    int e = blockIdx.x * blockDim.x + threadIdx.x;
    if (e < E) atomicAdd(&g_deg[dst[e]], 1);
}

// single-block shfl scan, 4 elements per thread -> g_rowstart
__global__ void k_scan(int NN) {
    __shared__ int warpsum[32];
    __shared__ int carry;
    const int tid = threadIdx.x;
    const int lane = tid & 31;
    const int wid = tid >> 5;
    if (tid == 0) carry = 0;
    __syncthreads();
    for (int base = 0; base < NN; base += 4096) {
        int i0 = base + tid * 4;
        int v0 = (i0 + 0 < NN) ? g_deg[i0 + 0] : 0;
        int v1 = (i0 + 1 < NN) ? g_deg[i0 + 1] : 0;
        int v2 = (i0 + 2 < NN) ? g_deg[i0 + 2] : 0;
        int v3 = (i0 + 3 < NN) ? g_deg[i0 + 3] : 0;
        int tsum = v0 + v1 + v2 + v3;
        int s = tsum;
#pragma unroll
        for (int o = 1; o < 32; o <<= 1) {
            int t = __shfl_up_sync(0xffffffffu, s, o);
            if (lane >= o) s += t;
        }
        if (lane == 31) warpsum[wid] = s;
        __syncthreads();
        if (wid == 0) {
            int ws = warpsum[lane];
#pragma unroll
            for (int o = 1; o < 32; o <<= 1) {
                int t = __shfl_up_sync(0xffffffffu, ws, o);
                if (lane >= o) ws += t;
            }
            warpsum[lane] = ws;
        }
        __syncthreads();
        int excl = s - tsum + (wid > 0 ? warpsum[wid - 1] : 0) + carry;
        if (i0 + 0 < NN) g_rowstart[i0 + 0] = excl; excl += v0;
        if (i0 + 1 < NN) g_rowstart[i0 + 1] = excl; excl += v1;
        if (i0 + 2 < NN) g_rowstart[i0 + 2] = excl; excl += v2;
        if (i0 + 3 < NN) g_rowstart[i0 + 3] = excl;
        int total = warpsum[31];
        __syncthreads();
        if (tid == 0) carry += total;
        __syncthreads();
    }
    if (tid == 0) g_rowstart[NN] = carry;
}

__global__ void k_fill(const int* __restrict__ src, const int* __restrict__ dst, int E) {
    int e = blockIdx.x * blockDim.x + threadIdx.x;
    if (e >= E) return;
    int d = dst[e];
    int pos = atomicAdd(&g_cursor[d], 1);
    g_csr_src[g_rowstart[d] + pos] = src[e];
}

// ---------------- fused single-pass softmax + aggregation --------------------
// 2 nodes per 512-thread block, warp per (node,head), lane per output feature.
// No max-subtraction: |ea| <~ 16 so exp() is safe in fp32; out = acc/(sum+eps)
// equals the reference's per-edge normalization.
__global__ void __launch_bounds__(512) k_aggr(float* __restrict__ out, int NN) {
    const int n = blockIdx.x * 2 + (threadIdx.x >> 8);
    if (n >= NN) return;
    const int head = (threadIdx.x >> 5) & 7;
    const int lane = threadIdx.x & 31;
    const int rs = g_rowstart[n];
    const int re = g_rowstart[n + 1];
    const float sd = g_sdst[n * HEADS_ + head];

    float acc = 0.f, wsum = 0.f;
    int i = rs;
    for (; i + 8 <= re; i += 8) {
        int sn[8];
        float an[8], hn[8];
#pragma unroll
        for (int q = 0; q < 8; q++) sn[q] = g_csr_src[i + q];
#pragma unroll
        for (int q = 0; q < 8; q++) an[q] = g_ssrc[sn[q] * HEADS_ + head] + sd;
#pragma unroll
        for (int q = 0; q < 8; q++) hn[q] = g_h[(size_t)sn[q] * HF_ + head * OUTF_ + lane];
#pragma unroll
        for (int q = 0; q < 8; q++) {
            float a = an[q];
            a = a > 0.f ? a : 0.2f * a;
            float e = __expf(a);
            wsum += e;
            acc = fmaf(e, hn[q], acc);
        }
    }
    for (; i < re; i++) {
        int s = g_csr_src[i];
        float ea = g_ssrc[s * HEADS_ + head] + sd;
        ea = ea > 0.f ? ea : 0.2f * ea;
        float e = __expf(ea);
        wsum += e;
        acc = fmaf(e, g_h[(size_t)s * HF_ + head * OUTF_ + lane], acc);
    }
    out[(size_t)n * HF_ + head * OUTF_ + lane] = acc / (wsum + 1e-8f);
}

// ---------------- launch -----------------------------------------------------
extern "C" void kernel_launch(void* const* d_in, const int* in_sizes, int n_in,
                              void* d_out, int out_size) {
    const float* x     = (const float*)d_in[0];
    const int*   ei    = (const int*)d_in[1];
    const float* W     = (const float*)d_in[2];
    const float* a_src = (const float*)d_in[3];
    const float* a_dst = (const float*)d_in[4];
    float* out = (float*)d_out;

    const int M = in_sizes[0] / INF_;     // 50000
    const int E = in_sizes[1] / 2;        // 800000
    const int* src = ei;
    const int* dst = ei + E;

    const int mblocks = (M + 127) / 128;  // 391; mblocks*128 <= MPAD

    k_wsplit<<<(HF_ * INF_ + 255) / 256, 256>>>(W);
    k_gemm_wmma<<<dim3(2, mblocks), 256>>>(x, a_src, a_dst, M);
    k_zero<<<(M + 255) / 256, 256>>>(M);
    k_count<<<(E + 255) / 256, 256>>>(dst, E);
    k_scan<<<1, 1024>>>(M);
    k_fill<<<(E + 255) / 256, 256>>>(src, dst, E);
    k_aggr<<<(M + 1) / 2, 512>>>(out, M);
}